// round 12
// baseline (speedup 1.0000x reference)
#include <cuda_runtime.h>
#include <cuda_bf16.h>
#include <cuda_fp16.h>
#include <math.h>
#include <stdint.h>

#define NN 50000
#define EE 800000
#define ET 850000      // EE + NN self loops
#define FIN 500
#define FINP 512       // K padded
#define HC 128         // H1*C1 = N
#define H1 8
#define C1 16
#define NC 7

// ---------------- scratch (device globals; no allocations allowed) -------------
__device__ float g_h1[NN * HC];
__device__ __align__(16) __half g_h1h[NN * HC];   // fp16 mirror for gather
__device__ float g_out1[NN * HC];
__device__ float g_asrc1[NN * H1];
__device__ float g_adst1[NN * H1];
__device__ float g_h2p[NN * 8];                   // {h2[0..6], asrc2}
__device__ float g_adst2[NN];
__device__ int   g_deg[NN];
__device__ int   g_off[NN + 1];
__device__ int   g_cur[NN];
__device__ int   g_srcsorted[ET];
__device__ __align__(16) unsigned short g_Bh[HC * FINP];  // W1^T hi (bf16), [n][k]
__device__ __align__(16) unsigned short g_Bl[HC * FINP];  // W1^T lo (bf16)

// ---------------- helpers -------------------------------------------------------
__device__ __forceinline__ uint32_t smem_u32(const void* p) {
    uint32_t a;
    asm("{ .reg .u64 t; cvta.to.shared.u64 t, %1; cvt.u32.u64 %0, t; }" : "=r"(a) : "l"(p));
    return a;
}

__device__ __forceinline__ void ldm_x4(uint32_t* r, uint32_t addr) {
    asm volatile("ldmatrix.sync.aligned.m8n8.x4.shared.b16 {%0,%1,%2,%3}, [%4];"
                 : "=r"(r[0]), "=r"(r[1]), "=r"(r[2]), "=r"(r[3]) : "r"(addr));
}

__device__ __forceinline__ void mma_bf16(float* c, const uint32_t* a, uint32_t b0, uint32_t b1) {
    asm volatile(
        "mma.sync.aligned.m16n8k16.row.col.f32.bf16.bf16.f32 "
        "{%0,%1,%2,%3}, {%4,%5,%6,%7}, {%8,%9}, {%0,%1,%2,%3};"
        : "+f"(c[0]), "+f"(c[1]), "+f"(c[2]), "+f"(c[3])
        : "r"(a[0]), "r"(a[1]), "r"(a[2]), "r"(a[3]), "r"(b0), "r"(b1));
}

__device__ __forceinline__ void cp16(uint32_t saddr, const void* g) {
    asm volatile("cp.async.ca.shared.global [%0], [%1], 16;" :: "r"(saddr), "l"(g) : "memory");
}

__device__ __forceinline__ float lrelu(float e) { return (e > 0.f) ? e : 0.2f * e; }

// ---------------- CSR build ----------------------------------------------------
__global__ void k_zero() {
    int i = blockIdx.x * blockDim.x + threadIdx.x;
    if (i < NN) { g_deg[i] = 0; g_cur[i] = 0; }
}

__global__ void k_hist(const int* __restrict__ ei) {
    int i = blockIdx.x * blockDim.x + threadIdx.x;
    if (i >= ET) return;
    int dst = (i < EE) ? ei[EE + i] : (i - EE);
    atomicAdd(&g_deg[dst], 1);
}

__global__ __launch_bounds__(1024)
void k_scan() {
    const int CH = (NN + 1023) / 1024;          // 49
    int tid  = threadIdx.x;
    int lane = tid & 31, wid = tid >> 5;
    int beg = tid * CH;
    int end = beg + CH; if (end > NN) end = NN;

    int sum = 0;
    for (int i = beg; i < end; i++) sum += g_deg[i];

    int v = sum;
#pragma unroll
    for (int o = 1; o < 32; o <<= 1) {
        int t = __shfl_up_sync(0xffffffffu, v, o);
        if (lane >= o) v += t;
    }
    __shared__ int wsum[32];
    if (lane == 31) wsum[wid] = v;
    __syncthreads();
    if (wid == 0) {
        int w = wsum[lane];
#pragma unroll
        for (int o = 1; o < 32; o <<= 1) {
            int t = __shfl_up_sync(0xffffffffu, w, o);
            if (lane >= o) w += t;
        }
        wsum[lane] = w;
    }
    __syncthreads();

    int excl = v - sum + (wid > 0 ? wsum[wid - 1] : 0);
    int run = excl;
    for (int i = beg; i < end; i++) {
        int d = g_deg[i];
        g_off[i] = run;
        run += d;
    }
    if (tid == 1023) g_off[NN] = run;
}

__global__ void k_scatter(const int* __restrict__ ei) {
    int i = blockIdx.x * blockDim.x + threadIdx.x;
    if (i >= ET) return;
    int src, dst;
    if (i < EE) { src = ei[i]; dst = ei[EE + i]; }
    else        { src = i - EE; dst = i - EE; }
    int slot = g_off[dst] + atomicAdd(&g_cur[dst], 1);
    g_srcsorted[slot] = src;
}

// ---------------- W1 transpose + bf16 hi/lo split ------------------------------
__global__ void k_split_w(const float* __restrict__ W1) {
    int idx = blockIdx.x * blockDim.x + threadIdx.x;   // n*512 + k
    if (idx >= HC * FINP) return;
    int n = idx >> 9, k = idx & (FINP - 1);
    float v = (k < FIN) ? W1[k * HC + n] : 0.f;
    uint32_t u = __float_as_uint(v);
    float h = __uint_as_float(u & 0xFFFF0000u);         // truncation split
    __nv_bfloat16 l = __float2bfloat16_rn(v - h);
    g_Bh[idx] = (unsigned short)(u >> 16);
    g_Bl[idx] = __bfloat16_as_ushort(l);
}

// ---------------- layer-1 GEMM: mma.sync bf16 3-pass, double-buffered ----------
#define SSTR 40            // smem row stride in bf16 elems (80B: conflict-free)
#define STAGE 40960
#define AH_OFF 0
#define AL_OFF 10240
#define BH_OFF 20480
#define BL_OFF 30720
#define GEMM_DSMEM (2 * STAGE)

__global__ __launch_bounds__(256, 2)
void k_gemm1_mma(const float* __restrict__ x) {
    extern __shared__ char dsm[];
    uint32_t sb = smem_u32(dsm);

    int tid = threadIdx.x;
    int wid = tid >> 5, lane = tid & 31;
    int warp_m = wid & 1;
    int warp_n = wid >> 1;
    int row0 = blockIdx.x * 128;

    float acc[4][4][4];
#pragma unroll
    for (int i = 0; i < 4; i++)
#pragma unroll
        for (int j = 0; j < 4; j++)
#pragma unroll
            for (int q = 0; q < 4; q++) acc[i][j][q] = 0.f;

    uint32_t a_lane_off = (uint32_t)((lane & 15) * SSTR + (lane >> 4) * 8) * 2;
    uint32_t b_lane_off = (uint32_t)((((lane & 16) >> 1) + (lane & 7)) * SSTR
                                     + ((lane & 8) ? 8 : 0)) * 2;

    float4 areg[4];

    auto issueB = [&](int s, int kt) {
#pragma unroll
        for (int i = 0; i < 2; i++) {
            int slot = tid + i * 256;
            int r  = slot >> 2;
            int kg = (slot & 3) * 8;
            uint32_t doff = sb + s * STAGE + (uint32_t)((r * SSTR + kg) * 2);
            cp16(doff + BH_OFF, g_Bh + r * FINP + kt * 32 + kg);
            cp16(doff + BL_OFF, g_Bl + r * FINP + kt * 32 + kg);
        }
        asm volatile("cp.async.commit_group;" ::: "memory");
    };

    auto loadA = [&](int kt) {
#pragma unroll
        for (int i = 0; i < 4; i++) {
            int slot = tid + i * 256;
            int r  = slot >> 3;
            int kf = (slot & 7) * 4;
            int gk = kt * 32 + kf;
            int gr = row0 + r;
            float4 v = make_float4(0.f, 0.f, 0.f, 0.f);
            if (gr < NN && gk < FIN)
                v = *(const float4*)(x + (size_t)gr * FIN + gk);
            areg[i] = v;
        }
    };

    auto storeA = [&](int s) {
        char* base = dsm + s * STAGE;
#pragma unroll
        for (int i = 0; i < 4; i++) {
            int slot = tid + i * 256;
            int r  = slot >> 3;
            int kf = (slot & 7) * 4;
            float4 v = areg[i];
            uint32_t u0 = __float_as_uint(v.x), u1 = __float_as_uint(v.y);
            uint32_t u2 = __float_as_uint(v.z), u3 = __float_as_uint(v.w);
            uint32_t h01, h23, lo01, lo23;
            asm("prmt.b32 %0, %1, %2, 0x7632;" : "=r"(h01) : "r"(u0), "r"(u1));
            asm("prmt.b32 %0, %1, %2, 0x7632;" : "=r"(h23) : "r"(u2), "r"(u3));
            float l0 = v.x - __uint_as_float(u0 & 0xFFFF0000u);
            float l1 = v.y - __uint_as_float(u1 & 0xFFFF0000u);
            float l2 = v.z - __uint_as_float(u2 & 0xFFFF0000u);
            float l3 = v.w - __uint_as_float(u3 & 0xFFFF0000u);
            asm("cvt.rn.bf16x2.f32 %0, %1, %2;" : "=r"(lo01) : "f"(l1), "f"(l0));
            asm("cvt.rn.bf16x2.f32 %0, %1, %2;" : "=r"(lo23) : "f"(l3), "f"(l2));
            *(uint2*)(base + AH_OFF + (r * SSTR + kf) * 2) = make_uint2(h01, h23);
            *(uint2*)(base + AL_OFF + (r * SSTR + kf) * 2) = make_uint2(lo01, lo23);
        }
    };

    issueB(0, 0);
    loadA(0);
    storeA(0);
    asm volatile("cp.async.wait_group 0;" ::: "memory");
    __syncthreads();

    for (int kt = 0; kt < 16; kt++) {
        int s = kt & 1, ns = s ^ 1;
        if (kt < 15) {
            issueB(ns, kt + 1);
            loadA(kt + 1);
        }

        uint32_t ab  = sb + s * STAGE + AH_OFF;
        uint32_t alb = sb + s * STAGE + AL_OFF;
        uint32_t bb  = sb + s * STAGE + BH_OFF;
        uint32_t blb = sb + s * STAGE + BL_OFF;

#pragma unroll
        for (int ks = 0; ks < 2; ks++) {
            uint32_t koff = (uint32_t)(ks * 16 * 2);
            uint32_t ah[4][4];
#pragma unroll
            for (int mt = 0; mt < 4; mt++)
                ldm_x4(ah[mt], ab + (uint32_t)((warp_m * 64 + mt * 16) * SSTR * 2)
                               + a_lane_off + koff);
            uint32_t bh[2][4];
#pragma unroll
            for (int bt = 0; bt < 2; bt++)
                ldm_x4(bh[bt], bb + (uint32_t)((warp_n * 32 + bt * 16) * SSTR * 2)
                               + b_lane_off + koff);
#pragma unroll
            for (int mt = 0; mt < 4; mt++)
#pragma unroll
                for (int nt = 0; nt < 4; nt++)
                    mma_bf16(acc[mt][nt], ah[mt],
                             bh[nt >> 1][(nt & 1) * 2], bh[nt >> 1][(nt & 1) * 2 + 1]);
            {
                uint32_t al[4][4];
#pragma unroll
                for (int mt = 0; mt < 4; mt++)
                    ldm_x4(al[mt], alb + (uint32_t)((warp_m * 64 + mt * 16) * SSTR * 2)
                                   + a_lane_off + koff);
#pragma unroll
                for (int mt = 0; mt < 4; mt++)
#pragma unroll
                    for (int nt = 0; nt < 4; nt++)
                        mma_bf16(acc[mt][nt], al[mt],
                                 bh[nt >> 1][(nt & 1) * 2], bh[nt >> 1][(nt & 1) * 2 + 1]);
            }
            {
                uint32_t bl[2][4];
#pragma unroll
                for (int bt = 0; bt < 2; bt++)
                    ldm_x4(bl[bt], blb + (uint32_t)((warp_n * 32 + bt * 16) * SSTR * 2)
                                   + b_lane_off + koff);
#pragma unroll
                for (int mt = 0; mt < 4; mt++)
#pragma unroll
                    for (int nt = 0; nt < 4; nt++)
                        mma_bf16(acc[mt][nt], ah[mt],
                                 bl[nt >> 1][(nt & 1) * 2], bl[nt >> 1][(nt & 1) * 2 + 1]);
            }
        }

        if (kt < 15) storeA(ns);
        asm volatile("cp.async.wait_group 0;" ::: "memory");
        __syncthreads();
    }

    // ---- epilogue: C fragment -> g_h1 (fp32) + g_h1h (fp16 gather mirror)
    int qrow = lane >> 2;
    int qcol = (lane & 3) * 2;
#pragma unroll
    for (int mt = 0; mt < 4; mt++) {
#pragma unroll
        for (int nt = 0; nt < 4; nt++) {
            int m = row0 + warp_m * 64 + mt * 16 + qrow;
            int n = warp_n * 32 + nt * 8 + qcol;
            if (m < NN) {
                *(float2*)&g_h1[(size_t)m * HC + n] =
                    make_float2(acc[mt][nt][0], acc[mt][nt][1]);
                *(__half2*)&g_h1h[(size_t)m * HC + n] =
                    __floats2half2_rn(acc[mt][nt][0], acc[mt][nt][1]);
            }
            int m2 = m + 8;
            if (m2 < NN) {
                *(float2*)&g_h1[(size_t)m2 * HC + n] =
                    make_float2(acc[mt][nt][2], acc[mt][nt][3]);
                *(__half2*)&g_h1h[(size_t)m2 * HC + n] =
                    __floats2half2_rn(acc[mt][nt][2], acc[mt][nt][3]);
            }
        }
    }
}

// ---------------- layer-1 attention logits (fp32 h1) ---------------------------
__global__ void k_attn1(const float* __restrict__ att_src, const float* __restrict__ att_dst) {
    int idx = blockIdx.x * blockDim.x + threadIdx.x;   // n*8 + h
    if (idx >= NN * H1) return;
    int h = idx & 7;
    const float* hp = g_h1 + (size_t)(idx >> 3) * HC + h * C1;
    const float* as = att_src + h * C1;
    const float* ad = att_dst + h * C1;
    float s = 0.f, d = 0.f;
#pragma unroll
    for (int c = 0; c < C1; c++) {
        float v = hp[c];
        s = fmaf(v, as[c], s);
        d = fmaf(v, ad[c], d);
    }
    g_asrc1[idx] = s;
    g_adst1[idx] = d;
}

// ---------------- layer-1 softmax-aggregate (fp16 gather, fp32 accum) ----------
__global__ __launch_bounds__(128)
void k_agg1(const float* __restrict__ b1) {
    int n = blockIdx.x * 4 + (threadIdx.x >> 5);     // 50000 = 12500*4 exact
    int lane = threadIdx.x & 31;

    int beg = g_off[n], end = g_off[n + 1];
    int head = lane >> 2;
    float adst = g_adst1[n * H1 + head];

    float s = 0.f;
    float4 acc = make_float4(0.f, 0.f, 0.f, 0.f);
    int j = beg;
    for (; j + 2 <= end; j += 2) {
        int s0 = g_srcsorted[j];
        int s1 = g_srcsorted[j + 1];
        float e0 = g_asrc1[s0 * H1 + head] + adst;
        float e1 = g_asrc1[s1 * H1 + head] + adst;
        uint2 r0 = *(const uint2*)(g_h1h + (size_t)s0 * HC + lane * 4);
        uint2 r1 = *(const uint2*)(g_h1h + (size_t)s1 * HC + lane * 4);
        float2 a0 = __half22float2(*(__half2*)&r0.x);
        float2 a1 = __half22float2(*(__half2*)&r0.y);
        float2 c0 = __half22float2(*(__half2*)&r1.x);
        float2 c1 = __half22float2(*(__half2*)&r1.y);
        float w0 = __expf(lrelu(e0));
        float w1 = __expf(lrelu(e1));
        s += w0 + w1;
        acc.x = fmaf(w0, a0.x, fmaf(w1, c0.x, acc.x));
        acc.y = fmaf(w0, a0.y, fmaf(w1, c0.y, acc.y));
        acc.z = fmaf(w0, a1.x, fmaf(w1, c1.x, acc.z));
        acc.w = fmaf(w0, a1.y, fmaf(w1, c1.y, acc.w));
    }
    if (j < end) {
        int s0 = g_srcsorted[j];
        float e0 = g_asrc1[s0 * H1 + head] + adst;
        uint2 r0 = *(const uint2*)(g_h1h + (size_t)s0 * HC + lane * 4);
        float2 a0 = __half22float2(*(__half2*)&r0.x);
        float2 a1 = __half22float2(*(__half2*)&r0.y);
        float w0 = __expf(lrelu(e0));
        s += w0;
        acc.x = fmaf(w0, a0.x, acc.x);
        acc.y = fmaf(w0, a0.y, acc.y);
        acc.z = fmaf(w0, a1.x, acc.z);
        acc.w = fmaf(w0, a1.y, acc.w);
    }
    float inv = 1.f / (s + 1e-16f);
    float4 bb = *(const float4*)(b1 + lane * 4);
    float4 o;
    o.x = fmaxf(acc.x * inv + bb.x, 0.f);
    o.y = fmaxf(acc.y * inv + bb.y, 0.f);
    o.z = fmaxf(acc.z * inv + bb.z, 0.f);
    o.w = fmaxf(acc.w * inv + bb.w, 0.f);
    *(float4*)(g_out1 + (size_t)n * HC + lane * 4) = o;
}

// ---------------- layer-2 GEMM (128->7) + packed state -------------------------
__global__ __launch_bounds__(256)
void k_l2(const float* __restrict__ W2, const float* __restrict__ att_src2,
          const float* __restrict__ att_dst2) {
    __shared__ float W2s[HC * NC];
    __shared__ float a2s[NC], a2d[NC];
    int tid = threadIdx.x;
    for (int t = tid; t < HC * NC; t += 256) W2s[t] = W2[t];
    if (tid < NC) { a2s[tid] = att_src2[tid]; a2d[tid] = att_dst2[tid]; }
    __syncthreads();

    int warp = blockIdx.x * 8 + (tid >> 5);
    int lane = tid & 31;
    if (warp >= NN) return;

    float4 v = *(const float4*)(g_out1 + (size_t)warp * HC + lane * 4);
    float hv[NC];
#pragma unroll
    for (int c = 0; c < NC; c++) {
        int i0 = lane * 4;
        float p = v.x * W2s[(i0 + 0) * NC + c]
                + v.y * W2s[(i0 + 1) * NC + c]
                + v.z * W2s[(i0 + 2) * NC + c]
                + v.w * W2s[(i0 + 3) * NC + c];
#pragma unroll
        for (int o = 16; o > 0; o >>= 1)
            p += __shfl_down_sync(0xffffffffu, p, o);
        hv[c] = p;
    }
    if (lane == 0) {
        float s = 0.f, d = 0.f;
#pragma unroll
        for (int c = 0; c < NC; c++) {
            g_h2p[warp * 8 + c] = hv[c];
            s = fmaf(hv[c], a2s[c], s);
            d = fmaf(hv[c], a2d[c], d);
        }
        g_h2p[warp * 8 + 7] = s;      // asrc2 packed in slot 7
        g_adst2[warp] = d;
    }
}

// ---------------- layer-2 softmax-aggregate (packed 32B/edge) ------------------
__global__ __launch_bounds__(128)
void k_agg2(float* __restrict__ out, const float* __restrict__ b2) {
    int tid = threadIdx.x;
    int lane = tid & 31;
    int g = tid >> 3;                 // 16 nodes per block
    int ch = tid & 7;                 // 0..6 = h2, 7 = asrc2 carrier
    int n = blockIdx.x * 16 + g;      // 50000 = 3125*16 exact
    int srcLane = (lane & ~7) | 7;

    int beg = g_off[n], end = g_off[n + 1];
    float adst = g_adst2[n];
    float s = 0.f, acc = 0.f;
    int j = beg;
    for (; j + 2 <= end; j += 2) {
        int s0 = g_srcsorted[j];
        int s1 = g_srcsorted[j + 1];
        float v0 = g_h2p[s0 * 8 + ch];
        float v1 = g_h2p[s1 * 8 + ch];
        float as0 = __shfl_sync(0xffffffffu, v0, srcLane);
        float as1 = __shfl_sync(0xffffffffu, v1, srcLane);
        float w0 = __expf(lrelu(as0 + adst));
        float w1 = __expf(lrelu(as1 + adst));
        s += w0 + w1;
        acc = fmaf(w0, v0, fmaf(w1, v1, acc));
    }
    if (j < end) {
        int s0 = g_srcsorted[j];
        float v0 = g_h2p[s0 * 8 + ch];
        float as0 = __shfl_sync(0xffffffffu, v0, srcLane);
        float w0 = __expf(lrelu(as0 + adst));
        s += w0;
        acc = fmaf(w0, v0, acc);
    }
    if (ch < NC)
        out[n * NC + ch] = acc / (s + 1e-16f) + b2[ch];
}

// ---------------- launch: fork CSR chain onto a side stream --------------------
extern "C" void kernel_launch(void* const* d_in, const int* in_sizes, int n_in,
                              void* d_out, int out_size) {
    const float* x        = (const float*)d_in[0];
    const int*   ei       = (const int*)d_in[1];     // int32 (JAX x64 disabled)
    const float* W1       = (const float*)d_in[2];
    const float* att_src1 = (const float*)d_in[3];
    const float* att_dst1 = (const float*)d_in[4];
    const float* b1       = (const float*)d_in[5];
    const float* W2       = (const float*)d_in[6];
    const float* att_src2 = (const float*)d_in[7];
    const float* att_dst2 = (const float*)d_in[8];
    const float* b2       = (const float*)d_in[9];
    float* out = (float*)d_out;

    cudaFuncSetAttribute(k_gemm1_mma, cudaFuncAttributeMaxDynamicSharedMemorySize,
                         GEMM_DSMEM);

    cudaStream_t s2;
    cudaEvent_t evFork, evJoin;
    cudaStreamCreateWithFlags(&s2, cudaStreamNonBlocking);
    cudaEventCreateWithFlags(&evFork, cudaEventDisableTiming);
    cudaEventCreateWithFlags(&evJoin, cudaEventDisableTiming);

    // fork: side stream inherits capture dependency from the legacy stream
    cudaEventRecord(evFork, 0);
    cudaStreamWaitEvent(s2, evFork, 0);

    // --- branch A (side stream): CSR build, independent of features
    k_zero<<<(NN + 255) / 256, 256, 0, s2>>>();
    k_hist<<<(ET + 255) / 256, 256, 0, s2>>>(ei);
    k_scan<<<1, 1024, 0, s2>>>();
    k_scatter<<<(ET + 255) / 256, 256, 0, s2>>>(ei);
    cudaEventRecord(evJoin, s2);

    // --- branch B (main stream): feature transform
    k_split_w<<<(HC * FINP + 255) / 256, 256>>>(W1);
    k_gemm1_mma<<<(NN + 127) / 128, 256, GEMM_DSMEM>>>(x);
    k_attn1<<<(NN * H1 + 255) / 256, 256>>>(att_src1, att_dst1);

    // join: aggregation needs both branches
    cudaStreamWaitEvent(0, evJoin, 0);
    k_agg1<<<NN / 4, 128>>>(b1);

    // layer 2
    k_l2<<<(NN + 7) / 8, 256>>>(W2, att_src2, att_dst2);
    k_agg2<<<NN / 16, 128>>>(out, b2);
}

// round 13
// speedup vs baseline: 1.0735x; 1.0735x over previous
#include <cuda_runtime.h>
#include <cuda_bf16.h>
#include <math.h>
#include <stdint.h>

#define NN 50000
#define EE 800000
#define ET 850000      // EE + NN self loops
#define FIN 500
#define FINP 512       // K padded
#define HC 128         // H1*C1 = N
#define H1 8
#define C1 16
#define NC 7

// ---------------- scratch (device globals; no allocations allowed) -------------
__device__ float g_h1[NN * HC];
__device__ float g_out1[NN * HC];
__device__ float g_asrc1[NN * H1];
__device__ float g_adst1[NN * H1];
__device__ float g_h2[NN * NC];
__device__ float g_asrc2[NN];
__device__ float g_adst2[NN];
__device__ int   g_deg[NN];
__device__ int   g_off[NN + 1];
__device__ int   g_cur[NN];
__device__ int   g_srcsorted[ET];
__device__ __align__(16) unsigned short g_Bh[HC * FINP];  // W1^T hi (bf16), [n][k]
__device__ __align__(16) unsigned short g_Bl[HC * FINP];  // W1^T lo (bf16)

// ---------------- helpers -------------------------------------------------------
__device__ __forceinline__ uint32_t smem_u32(const void* p) {
    uint32_t a;
    asm("{ .reg .u64 t; cvta.to.shared.u64 t, %1; cvt.u32.u64 %0, t; }" : "=r"(a) : "l"(p));
    return a;
}

__device__ __forceinline__ void ldm_x4(uint32_t* r, uint32_t addr) {
    asm volatile("ldmatrix.sync.aligned.m8n8.x4.shared.b16 {%0,%1,%2,%3}, [%4];"
                 : "=r"(r[0]), "=r"(r[1]), "=r"(r[2]), "=r"(r[3]) : "r"(addr));
}

__device__ __forceinline__ void mma_bf16(float* c, const uint32_t* a, uint32_t b0, uint32_t b1) {
    asm volatile(
        "mma.sync.aligned.m16n8k16.row.col.f32.bf16.bf16.f32 "
        "{%0,%1,%2,%3}, {%4,%5,%6,%7}, {%8,%9}, {%0,%1,%2,%3};"
        : "+f"(c[0]), "+f"(c[1]), "+f"(c[2]), "+f"(c[3])
        : "r"(a[0]), "r"(a[1]), "r"(a[2]), "r"(a[3]), "r"(b0), "r"(b1));
}

__device__ __forceinline__ void cp16(uint32_t saddr, const void* g) {
    asm volatile("cp.async.ca.shared.global [%0], [%1], 16;" :: "r"(saddr), "l"(g) : "memory");
}

__device__ __forceinline__ float lrelu(float e) { return (e > 0.f) ? e : 0.2f * e; }

// ---------------- CSR build ----------------------------------------------------
__global__ void k_zero() {
    int i = blockIdx.x * blockDim.x + threadIdx.x;
    if (i < NN) { g_deg[i] = 0; g_cur[i] = 0; }
}

__global__ void k_hist(const int* __restrict__ ei) {
    int i = blockIdx.x * blockDim.x + threadIdx.x;
    if (i >= ET) return;
    int dst = (i < EE) ? ei[EE + i] : (i - EE);
    atomicAdd(&g_deg[dst], 1);
}

__global__ __launch_bounds__(1024)
void k_scan() {
    const int CH = (NN + 1023) / 1024;          // 49
    int tid  = threadIdx.x;
    int lane = tid & 31, wid = tid >> 5;
    int beg = tid * CH;
    int end = beg + CH; if (end > NN) end = NN;

    int sum = 0;
    for (int i = beg; i < end; i++) sum += g_deg[i];

    int v = sum;
#pragma unroll
    for (int o = 1; o < 32; o <<= 1) {
        int t = __shfl_up_sync(0xffffffffu, v, o);
        if (lane >= o) v += t;
    }
    __shared__ int wsum[32];
    if (lane == 31) wsum[wid] = v;
    __syncthreads();
    if (wid == 0) {
        int w = wsum[lane];
#pragma unroll
        for (int o = 1; o < 32; o <<= 1) {
            int t = __shfl_up_sync(0xffffffffu, w, o);
            if (lane >= o) w += t;
        }
        wsum[lane] = w;
    }
    __syncthreads();

    int excl = v - sum + (wid > 0 ? wsum[wid - 1] : 0);
    int run = excl;
    for (int i = beg; i < end; i++) {
        int d = g_deg[i];
        g_off[i] = run;
        run += d;
    }
    if (tid == 1023) g_off[NN] = run;
}

__global__ void k_scatter(const int* __restrict__ ei) {
    int i = blockIdx.x * blockDim.x + threadIdx.x;
    if (i >= ET) return;
    int src, dst;
    if (i < EE) { src = ei[i]; dst = ei[EE + i]; }
    else        { src = i - EE; dst = i - EE; }
    int slot = g_off[dst] + atomicAdd(&g_cur[dst], 1);
    g_srcsorted[slot] = src;
}

// ---------------- W1 transpose + bf16 hi/lo split ------------------------------
__global__ void k_split_w(const float* __restrict__ W1) {
    int idx = blockIdx.x * blockDim.x + threadIdx.x;   // n*512 + k
    if (idx >= HC * FINP) return;
    int n = idx >> 9, k = idx & (FINP - 1);
    float v = (k < FIN) ? W1[k * HC + n] : 0.f;
    uint32_t u = __float_as_uint(v);
    float h = __uint_as_float(u & 0xFFFF0000u);         // truncation split
    __nv_bfloat16 l = __float2bfloat16_rn(v - h);
    g_Bh[idx] = (unsigned short)(u >> 16);
    g_Bl[idx] = __bfloat16_as_ushort(l);
}

// ---------------- layer-1 GEMM: mma.sync bf16 3-pass, double-buffered ----------
#define SSTR 40            // smem row stride in bf16 elems (80B: conflict-free)
#define STAGE 40960
#define AH_OFF 0
#define AL_OFF 10240
#define BH_OFF 20480
#define BL_OFF 30720
#define GEMM_DSMEM (2 * STAGE)

__global__ __launch_bounds__(256, 2)
void k_gemm1_mma(const float* __restrict__ x) {
    extern __shared__ char dsm[];
    uint32_t sb = smem_u32(dsm);

    int tid = threadIdx.x;
    int wid = tid >> 5, lane = tid & 31;
    int warp_m = wid & 1;
    int warp_n = wid >> 1;
    int row0 = blockIdx.x * 128;

    float acc[4][4][4];
#pragma unroll
    for (int i = 0; i < 4; i++)
#pragma unroll
        for (int j = 0; j < 4; j++)
#pragma unroll
            for (int q = 0; q < 4; q++) acc[i][j][q] = 0.f;

    uint32_t a_lane_off = (uint32_t)((lane & 15) * SSTR + (lane >> 4) * 8) * 2;
    uint32_t b_lane_off = (uint32_t)((((lane & 16) >> 1) + (lane & 7)) * SSTR
                                     + ((lane & 8) ? 8 : 0)) * 2;

    float4 areg[4];

    auto issueB = [&](int s, int kt) {
#pragma unroll
        for (int i = 0; i < 2; i++) {
            int slot = tid + i * 256;
            int r  = slot >> 2;
            int kg = (slot & 3) * 8;
            uint32_t doff = sb + s * STAGE + (uint32_t)((r * SSTR + kg) * 2);
            cp16(doff + BH_OFF, g_Bh + r * FINP + kt * 32 + kg);
            cp16(doff + BL_OFF, g_Bl + r * FINP + kt * 32 + kg);
        }
        asm volatile("cp.async.commit_group;" ::: "memory");
    };

    auto loadA = [&](int kt) {
#pragma unroll
        for (int i = 0; i < 4; i++) {
            int slot = tid + i * 256;
            int r  = slot >> 3;
            int kf = (slot & 7) * 4;
            int gk = kt * 32 + kf;
            int gr = row0 + r;
            float4 v = make_float4(0.f, 0.f, 0.f, 0.f);
            if (gr < NN && gk < FIN)
                v = *(const float4*)(x + (size_t)gr * FIN + gk);
            areg[i] = v;
        }
    };

    auto storeA = [&](int s) {
        char* base = dsm + s * STAGE;
#pragma unroll
        for (int i = 0; i < 4; i++) {
            int slot = tid + i * 256;
            int r  = slot >> 3;
            int kf = (slot & 7) * 4;
            float4 v = areg[i];
            uint32_t u0 = __float_as_uint(v.x), u1 = __float_as_uint(v.y);
            uint32_t u2 = __float_as_uint(v.z), u3 = __float_as_uint(v.w);
            uint32_t h01, h23, lo01, lo23;
            asm("prmt.b32 %0, %1, %2, 0x7632;" : "=r"(h01) : "r"(u0), "r"(u1));
            asm("prmt.b32 %0, %1, %2, 0x7632;" : "=r"(h23) : "r"(u2), "r"(u3));
            float l0 = v.x - __uint_as_float(u0 & 0xFFFF0000u);
            float l1 = v.y - __uint_as_float(u1 & 0xFFFF0000u);
            float l2 = v.z - __uint_as_float(u2 & 0xFFFF0000u);
            float l3 = v.w - __uint_as_float(u3 & 0xFFFF0000u);
            asm("cvt.rn.bf16x2.f32 %0, %1, %2;" : "=r"(lo01) : "f"(l1), "f"(l0));
            asm("cvt.rn.bf16x2.f32 %0, %1, %2;" : "=r"(lo23) : "f"(l3), "f"(l2));
            *(uint2*)(base + AH_OFF + (r * SSTR + kf) * 2) = make_uint2(h01, h23);
            *(uint2*)(base + AL_OFF + (r * SSTR + kf) * 2) = make_uint2(lo01, lo23);
        }
    };

    issueB(0, 0);
    loadA(0);
    storeA(0);
    asm volatile("cp.async.wait_group 0;" ::: "memory");
    __syncthreads();

    for (int kt = 0; kt < 16; kt++) {
        int s = kt & 1, ns = s ^ 1;
        if (kt < 15) {
            issueB(ns, kt + 1);
            loadA(kt + 1);
        }

        uint32_t ab  = sb + s * STAGE + AH_OFF;
        uint32_t alb = sb + s * STAGE + AL_OFF;
        uint32_t bb  = sb + s * STAGE + BH_OFF;
        uint32_t blb = sb + s * STAGE + BL_OFF;

#pragma unroll
        for (int ks = 0; ks < 2; ks++) {
            uint32_t koff = (uint32_t)(ks * 16 * 2);
            uint32_t ah[4][4];
#pragma unroll
            for (int mt = 0; mt < 4; mt++)
                ldm_x4(ah[mt], ab + (uint32_t)((warp_m * 64 + mt * 16) * SSTR * 2)
                               + a_lane_off + koff);
            uint32_t bh[2][4];
#pragma unroll
            for (int bt = 0; bt < 2; bt++)
                ldm_x4(bh[bt], bb + (uint32_t)((warp_n * 32 + bt * 16) * SSTR * 2)
                               + b_lane_off + koff);
#pragma unroll
            for (int mt = 0; mt < 4; mt++)
#pragma unroll
                for (int nt = 0; nt < 4; nt++)
                    mma_bf16(acc[mt][nt], ah[mt],
                             bh[nt >> 1][(nt & 1) * 2], bh[nt >> 1][(nt & 1) * 2 + 1]);
            {
                uint32_t al[4][4];
#pragma unroll
                for (int mt = 0; mt < 4; mt++)
                    ldm_x4(al[mt], alb + (uint32_t)((warp_m * 64 + mt * 16) * SSTR * 2)
                                   + a_lane_off + koff);
#pragma unroll
                for (int mt = 0; mt < 4; mt++)
#pragma unroll
                    for (int nt = 0; nt < 4; nt++)
                        mma_bf16(acc[mt][nt], al[mt],
                                 bh[nt >> 1][(nt & 1) * 2], bh[nt >> 1][(nt & 1) * 2 + 1]);
            }
            {
                uint32_t bl[2][4];
#pragma unroll
                for (int bt = 0; bt < 2; bt++)
                    ldm_x4(bl[bt], blb + (uint32_t)((warp_n * 32 + bt * 16) * SSTR * 2)
                                   + b_lane_off + koff);
#pragma unroll
                for (int mt = 0; mt < 4; mt++)
#pragma unroll
                    for (int nt = 0; nt < 4; nt++)
                        mma_bf16(acc[mt][nt], ah[mt],
                                 bl[nt >> 1][(nt & 1) * 2], bl[nt >> 1][(nt & 1) * 2 + 1]);
            }
        }

        if (kt < 15) storeA(ns);
        asm volatile("cp.async.wait_group 0;" ::: "memory");
        __syncthreads();
    }

    // ---- epilogue: C fragment -> g_h1
    int qrow = lane >> 2;
    int qcol = (lane & 3) * 2;
#pragma unroll
    for (int mt = 0; mt < 4; mt++) {
#pragma unroll
        for (int nt = 0; nt < 4; nt++) {
            int m = row0 + warp_m * 64 + mt * 16 + qrow;
            int n = warp_n * 32 + nt * 8 + qcol;
            if (m < NN)
                *(float2*)&g_h1[(size_t)m * HC + n] =
                    make_float2(acc[mt][nt][0], acc[mt][nt][1]);
            int m2 = m + 8;
            if (m2 < NN)
                *(float2*)&g_h1[(size_t)m2 * HC + n] =
                    make_float2(acc[mt][nt][2], acc[mt][nt][3]);
        }
    }
}

// ---------------- layer-1 attention logits -------------------------------------
__global__ void k_attn1(const float* __restrict__ att_src, const float* __restrict__ att_dst) {
    int idx = blockIdx.x * blockDim.x + threadIdx.x;   // n*8 + h
    if (idx >= NN * H1) return;
    int h = idx & 7;
    const float* hp = g_h1 + (size_t)(idx >> 3) * HC + h * C1;
    const float* as = att_src + h * C1;
    const float* ad = att_dst + h * C1;
    float s = 0.f, d = 0.f;
#pragma unroll
    for (int c = 0; c < C1; c++) {
        float v = hp[c];
        s = fmaf(v, as[c], s);
        d = fmaf(v, ad[c], d);
    }
    g_asrc1[idx] = s;
    g_adst1[idx] = d;
}

// ---------------- layer-1 softmax-aggregate (warp/node, MLP-4 unroll) ----------
__global__ __launch_bounds__(128)
void k_agg1(const float* __restrict__ b1) {
    int n = blockIdx.x * 4 + (threadIdx.x >> 5);     // 50000 = 12500*4 exact
    int lane = threadIdx.x & 31;

    int beg = g_off[n], end = g_off[n + 1];
    int head = lane >> 2;
    float adst = g_adst1[n * H1 + head];

    float s = 0.f;
    float4 acc = make_float4(0.f, 0.f, 0.f, 0.f);
    int j = beg;
    // unroll 4: all indices first, then all gathers, then consume -> MLP ~4-8
    for (; j + 4 <= end; j += 4) {
        int s0 = g_srcsorted[j];
        int s1 = g_srcsorted[j + 1];
        int s2 = g_srcsorted[j + 2];
        int s3 = g_srcsorted[j + 3];
        float e0 = g_asrc1[s0 * H1 + head];
        float e1 = g_asrc1[s1 * H1 + head];
        float e2 = g_asrc1[s2 * H1 + head];
        float e3 = g_asrc1[s3 * H1 + head];
        float4 h0 = *(const float4*)(g_h1 + (size_t)s0 * HC + lane * 4);
        float4 h1v = *(const float4*)(g_h1 + (size_t)s1 * HC + lane * 4);
        float4 h2v = *(const float4*)(g_h1 + (size_t)s2 * HC + lane * 4);
        float4 h3v = *(const float4*)(g_h1 + (size_t)s3 * HC + lane * 4);
        float w0 = __expf(lrelu(e0 + adst));
        float w1 = __expf(lrelu(e1 + adst));
        float w2 = __expf(lrelu(e2 + adst));
        float w3 = __expf(lrelu(e3 + adst));
        s += (w0 + w1) + (w2 + w3);
        acc.x = fmaf(w0, h0.x, fmaf(w1, h1v.x, fmaf(w2, h2v.x, fmaf(w3, h3v.x, acc.x))));
        acc.y = fmaf(w0, h0.y, fmaf(w1, h1v.y, fmaf(w2, h2v.y, fmaf(w3, h3v.y, acc.y))));
        acc.z = fmaf(w0, h0.z, fmaf(w1, h1v.z, fmaf(w2, h2v.z, fmaf(w3, h3v.z, acc.z))));
        acc.w = fmaf(w0, h0.w, fmaf(w1, h1v.w, fmaf(w2, h2v.w, fmaf(w3, h3v.w, acc.w))));
    }
    for (; j < end; j++) {
        int s0 = g_srcsorted[j];
        float e0 = g_asrc1[s0 * H1 + head] + adst;
        float4 h0 = *(const float4*)(g_h1 + (size_t)s0 * HC + lane * 4);
        float w0 = __expf(lrelu(e0));
        s += w0;
        acc.x = fmaf(w0, h0.x, acc.x);
        acc.y = fmaf(w0, h0.y, acc.y);
        acc.z = fmaf(w0, h0.z, acc.z);
        acc.w = fmaf(w0, h0.w, acc.w);
    }
    float inv = 1.f / (s + 1e-16f);
    float4 bb = *(const float4*)(b1 + lane * 4);
    float4 o;
    o.x = fmaxf(acc.x * inv + bb.x, 0.f);
    o.y = fmaxf(acc.y * inv + bb.y, 0.f);
    o.z = fmaxf(acc.z * inv + bb.z, 0.f);
    o.w = fmaxf(acc.w * inv + bb.w, 0.f);
    *(float4*)(g_out1 + (size_t)n * HC + lane * 4) = o;
}

// ---------------- layer-2 GEMM (128->7) + attention logits ---------------------
__global__ __launch_bounds__(256)
void k_l2(const float* __restrict__ W2, const float* __restrict__ att_src2,
          const float* __restrict__ att_dst2) {
    __shared__ float W2s[HC * NC];
    __shared__ float a2s[NC], a2d[NC];
    int tid = threadIdx.x;
    for (int t = tid; t < HC * NC; t += 256) W2s[t] = W2[t];
    if (tid < NC) { a2s[tid] = att_src2[tid]; a2d[tid] = att_dst2[tid]; }
    __syncthreads();

    int warp = blockIdx.x * 8 + (tid >> 5);
    int lane = tid & 31;
    if (warp >= NN) return;

    float4 v = *(const float4*)(g_out1 + (size_t)warp * HC + lane * 4);
    float hv[NC];
#pragma unroll
    for (int c = 0; c < NC; c++) {
        int i0 = lane * 4;
        float p = v.x * W2s[(i0 + 0) * NC + c]
                + v.y * W2s[(i0 + 1) * NC + c]
                + v.z * W2s[(i0 + 2) * NC + c]
                + v.w * W2s[(i0 + 3) * NC + c];
#pragma unroll
        for (int o = 16; o > 0; o >>= 1)
            p += __shfl_down_sync(0xffffffffu, p, o);
        hv[c] = p;
    }
    if (lane == 0) {
        float s = 0.f, d = 0.f;
#pragma unroll
        for (int c = 0; c < NC; c++) {
            g_h2[warp * NC + c] = hv[c];
            s = fmaf(hv[c], a2s[c], s);
            d = fmaf(hv[c], a2d[c], d);
        }
        g_asrc2[warp] = s;
        g_adst2[warp] = d;
    }
}

// ---------------- layer-2 softmax-aggregate (direct exp, unroll 2) -------------
__global__ __launch_bounds__(128)
void k_agg2(float* __restrict__ out, const float* __restrict__ b2) {
    int tid = threadIdx.x;
    int g = tid >> 3;                 // 16 nodes per block
    int ch = tid & 7;                 // 0..6 used
    int n = blockIdx.x * 16 + g;      // 50000 = 3125*16 exact
    if (ch >= NC) return;

    int beg = g_off[n], end = g_off[n + 1];
    float adst = g_adst2[n];
    float s = 0.f, acc = 0.f;
    int j = beg;
    for (; j + 2 <= end; j += 2) {
        int s0 = g_srcsorted[j];
        int s1 = g_srcsorted[j + 1];
        float e0 = g_asrc2[s0] + adst;
        float e1 = g_asrc2[s1] + adst;
        float h0 = g_h2[s0 * NC + ch];
        float h1 = g_h2[s1 * NC + ch];
        float w0 = __expf(lrelu(e0));
        float w1 = __expf(lrelu(e1));
        s += w0 + w1;
        acc = fmaf(w0, h0, fmaf(w1, h1, acc));
    }
    if (j < end) {
        int s0 = g_srcsorted[j];
        float e0 = g_asrc2[s0] + adst;
        float h0 = g_h2[s0 * NC + ch];
        float w0 = __expf(lrelu(e0));
        s += w0;
        acc = fmaf(w0, h0, acc);
    }
    out[n * NC + ch] = acc / (s + 1e-16f) + b2[ch];
}

// ---------------- launch: fork CSR chain onto a side stream --------------------
extern "C" void kernel_launch(void* const* d_in, const int* in_sizes, int n_in,
                              void* d_out, int out_size) {
    const float* x        = (const float*)d_in[0];
    const int*   ei       = (const int*)d_in[1];     // int32 (JAX x64 disabled)
    const float* W1       = (const float*)d_in[2];
    const float* att_src1 = (const float*)d_in[3];
    const float* att_dst1 = (const float*)d_in[4];
    const float* b1       = (const float*)d_in[5];
    const float* W2       = (const float*)d_in[6];
    const float* att_src2 = (const float*)d_in[7];
    const float* att_dst2 = (const float*)d_in[8];
    const float* b2       = (const float*)d_in[9];
    float* out = (float*)d_out;

    cudaFuncSetAttribute(k_gemm1_mma, cudaFuncAttributeMaxDynamicSharedMemorySize,
                         GEMM_DSMEM);

    cudaStream_t s2;
    cudaEvent_t evFork, evJoin;
    cudaStreamCreateWithFlags(&s2, cudaStreamNonBlocking);
    cudaEventCreateWithFlags(&evFork, cudaEventDisableTiming);
    cudaEventCreateWithFlags(&evJoin, cudaEventDisableTiming);

    // fork: side stream inherits capture dependency from the legacy stream
    cudaEventRecord(evFork, 0);
    cudaStreamWaitEvent(s2, evFork, 0);

    // --- branch A (side stream): CSR build, independent of features
    k_zero<<<(NN + 255) / 256, 256, 0, s2>>>();
    k_hist<<<(ET + 255) / 256, 256, 0, s2>>>(ei);
    k_scan<<<1, 1024, 0, s2>>>();
    k_scatter<<<(ET + 255) / 256, 256, 0, s2>>>(ei);
    cudaEventRecord(evJoin, s2);

    // --- branch B (main stream): feature transform
    k_split_w<<<(HC * FINP + 255) / 256, 256>>>(W1);
    k_gemm1_mma<<<(NN + 127) / 128, 256, GEMM_DSMEM>>>(x);
    k_attn1<<<(NN * H1 + 255) / 256, 256>>>(att_src1, att_dst1);

    // join: aggregation needs both branches
    cudaStreamWaitEvent(0, evJoin, 0);
    k_agg1<<<NN / 4, 128>>>(b1);

    // layer 2
    k_l2<<<(NN + 7) / 8, 256>>>(W2, att_src2, att_dst2);
    k_agg2<<<NN / 16, 128>>>(out, b2);
}